// round 12
// baseline (speedup 1.0000x reference)
#include <cuda_runtime.h>

// 16k -> 24k polyphase resampler (torchaudio/kaldi defaults).
// in_unit=2, out_unit=3 phases, first_indices={-6,-5,-4}, W=13 taps.
// out[c, n] = sum_j x[c, (n%3 - 6) + 2*(n/3) + j] * w[n%3][j], zero-padded x.
//
// Warp-halo T=4 tiles, 2 far-apart tiles per thread (t, t+250000), all 4
// LDG.128 front-batched for MLP. Tile-2's data is PARKED in padded smem
// (own-thread STS/LDS, no sync, conflict-free layout) during tile-1's pass so
// peak register liveness stays ~40 -> 6 blocks/SM (R11 kept it in regs: 48
// regs, occ 50.6%). Loads plain __ldg (edge-halo L2 reuse); stores .cs.
// Weights in __constant__. 250000 % 32 == 0 -> warps never straddle channels.

#define C_CH    8
#define NPHASE  3
#define WTAPS   13
#define OUT_PT  12          // outputs per tile (4 units x 3 phases)
#define BLK     256
#define HALF    250000      // tiles per channel-half (500000 total per ch)
#define PSLOT(i) ((i) + ((i) >> 3))   // padded float4 slot (conflict-free)

__constant__ float cw[NPHASE * WTAPS];

// Shuffle-halo + compute + store for one T=4 tile. A/B already loaded.
__device__ __forceinline__ void tile_pass(
    float4 A, float4 B, int t, int lane,
    const float* __restrict__ xc, float* __restrict__ out_c,
    int L, int tot)
{
    const int g0 = 8 * t;
    const float4* p = reinterpret_cast<const float4*>(xc + g0);

    // xin[k] = x[8t - 8 + k]; taps use xin[2..22].
    float xin[23];
    const unsigned m = 0xffffffffu;
    xin[2]  = __shfl_up_sync(m, A.z, 1);
    xin[3]  = __shfl_up_sync(m, A.w, 1);
    xin[4]  = __shfl_up_sync(m, B.x, 1);
    xin[5]  = __shfl_up_sync(m, B.y, 1);
    xin[6]  = __shfl_up_sync(m, B.z, 1);
    xin[7]  = __shfl_up_sync(m, B.w, 1);
    xin[8]  = A.x; xin[9]  = A.y; xin[10] = A.z; xin[11] = A.w;
    xin[12] = B.x; xin[13] = B.y; xin[14] = B.z; xin[15] = B.w;
    xin[16] = __shfl_down_sync(m, A.x, 1);
    xin[17] = __shfl_down_sync(m, A.y, 1);
    xin[18] = __shfl_down_sync(m, A.z, 1);
    xin[19] = __shfl_down_sync(m, A.w, 1);
    xin[20] = __shfl_down_sync(m, B.x, 1);
    xin[21] = __shfl_down_sync(m, B.y, 1);
    xin[22] = __shfl_down_sync(m, B.z, 1);

    // Warp-edge halo patch (after the shuffle chain; R8: before = regression).
    if (lane == 0) {
        const int gl = g0 - 8;
        if (gl >= 0) {
            float4 PA = __ldg(&p[-2]);
            float4 PB = __ldg(&p[-1]);
            xin[2] = PA.z; xin[3] = PA.w;
            xin[4] = PB.x; xin[5] = PB.y; xin[6] = PB.z; xin[7] = PB.w;
        } else {
#pragma unroll
            for (int q = 2; q < 8; q++) {
                int g = gl + q;
                xin[q] = (g >= 0 && g < L) ? xc[g] : 0.0f;
            }
        }
    }
    if (lane == 31) {
        const int gr = g0 + 8;
        if (gr + 8 <= L) {
            float4 NA = __ldg(&p[2]);
            float4 NB = __ldg(&p[3]);
            xin[16] = NA.x; xin[17] = NA.y; xin[18] = NA.z; xin[19] = NA.w;
            xin[20] = NB.x; xin[21] = NB.y; xin[22] = NB.z;
        } else {
#pragma unroll
            for (int q = 0; q < 7; q++) {
                int g = gr + q;
                xin[16 + q] = (g >= 0 && g < L) ? xc[g] : 0.0f;
            }
        }
    }

    const int n0 = t * OUT_PT;
    if (n0 >= tot) return;
    float4* po = reinterpret_cast<float4*>(out_c + n0);
#pragma unroll
    for (int q = 0; q < 3; q++) {
        float o4[4];
#pragma unroll
        for (int r = 0; r < 4; r++) {
            const int n = 4 * q + r;
            const int u = n / 3;
            const int i = n % 3;
            const int base = 2 + i + 2 * u;
            float s = 0.0f;
#pragma unroll
            for (int j = 0; j < WTAPS; j++)
                s = fmaf(xin[base + j], cw[i * WTAPS + j], s);
            o4[r] = s;
        }
        __stcs(&po[q], make_float4(o4[0], o4[1], o4[2], o4[3]));
    }
}

__global__ __launch_bounds__(BLK, 6) void resample_16_24_kernel(
    const float* __restrict__ x, float* __restrict__ out, int L, int tot)
{
    // Parking lot for tile-2 data (own-thread access only, no sync).
    __shared__ float4 parkA[BLK + (BLK >> 3)];
    __shared__ float4 parkB[BLK + (BLK >> 3)];

    const int c = blockIdx.y;
    const int tid = threadIdx.x;
    const int lane = tid & 31;
    const int t1 = blockIdx.x * BLK + tid;   // tile in first half
    const int t2 = t1 + HALF;                // tile in second half

    const float* xc = x + (size_t)c * (size_t)L;
    float* out_c = out + (size_t)c * (size_t)tot;

    // Front-batch all 4 global loads (both tiles) for MLP, then park tile-2's
    // data in smem so register liveness through tile-1 stays at the 1-tile level.
    const int g1 = 8 * t1;
    const int g2 = 8 * t2;
    float4 A, B;
    {
        float4 A2, B2;
        if (g2 + 8 <= L) {
            const float4* p2 = reinterpret_cast<const float4*>(xc + g2);
            A2 = __ldg(&p2[0]); B2 = __ldg(&p2[1]);
        } else {
            A2 = make_float4(0.f, 0.f, 0.f, 0.f);
            B2 = make_float4(0.f, 0.f, 0.f, 0.f);
        }
        if (g1 + 8 <= L) {
            const float4* p1 = reinterpret_cast<const float4*>(xc + g1);
            A = __ldg(&p1[0]); B = __ldg(&p1[1]);
        } else {
            A = make_float4(0.f, 0.f, 0.f, 0.f);
            B = make_float4(0.f, 0.f, 0.f, 0.f);
        }
        parkA[PSLOT(tid)] = A2;
        parkB[PSLOT(tid)] = B2;
    }

    tile_pass(A, B, t1, lane, xc, out_c, L, tot);

    A = parkA[PSLOT(tid)];
    B = parkB[PSLOT(tid)];
    tile_pass(A, B, t2, lane, xc, out_c, L, tot);
}

extern "C" void kernel_launch(void* const* d_in, const int* in_sizes, int n_in,
                              void* d_out, int out_size)
{
    const float* x   = (const float*)d_in[0];
    const float* wgt = (const float*)d_in[1];
    float* out = (float*)d_out;

    const int L   = in_sizes[0] / C_CH;   // 4,000,000
    const int tot = out_size   / C_CH;    // 6,000,000 (divisible by 12)

    // Stage filter bank into constant memory (DtoD, on captured legacy stream)
    cudaMemcpyToSymbolAsync(cw, wgt, NPHASE * WTAPS * sizeof(float), 0,
                            cudaMemcpyDeviceToDevice, 0);

    const int bx = (HALF + BLK - 1) / BLK;   // 977 blocks covers 250,112 >= HALF
    dim3 grid(bx, C_CH);
    resample_16_24_kernel<<<grid, BLK>>>(x, out, L, tot);
}